// round 8
// baseline (speedup 1.0000x reference)
#include <cuda_runtime.h>
#include <cstdint>

// CBFHalfspace collapses analytically:
//   h(x) = [1+x0, 1-x0, 1+x1, 1-x1];  Lfh = Lf2h = 0, LgLfh = (0,0)  (affine h, A col-sums 0)
// Output row: [1+x0, 1-x0, 1+x1, 1-x1, 0,0,0,0]. f, g are dead inputs.
//
// R6c: cp.async double-buffered pipeline, grid-stride warps (resubmit after infra fail).
//   Warp-private tiles of 64 rows. While computing+storing tile t from stage s,
//   the next tile's 112 float4 are already streaming into stage s^1 via
//   cp.async.cg (L1-bypass, no prefetch registers). wait_group 1 + syncwarp
//   releases tile t. Keeps the per-warp DRAM request stream continuously dense.

#define THREADS 256
#define WARPS 8
#define ROWS_PER_TILE 64
#define F4_PER_TILE 112        // 64*7/4
#define OUT4_PER_TILE 128      // 64*2

__device__ __forceinline__ void cp16(void* smem, const void* gmem) {
    unsigned int s = (unsigned int)__cvta_generic_to_shared(smem);
    asm volatile("cp.async.cg.shared.global [%0], [%1], 16;\n" :: "r"(s), "l"(gmem));
}
__device__ __forceinline__ void cp_commit() { asm volatile("cp.async.commit_group;\n"); }
__device__ __forceinline__ void cp_wait1()  { asm volatile("cp.async.wait_group 1;\n" ::: "memory"); }

__global__ void __launch_bounds__(THREADS)
cbf_kernel(const float4* __restrict__ x4, float4* __restrict__ out4,
           int n, int numTiles)
{
    __shared__ float4 buf[WARPS][2][F4_PER_TILE];   // 28 KB

    const int lane = threadIdx.x & 31;
    const int wid  = threadIdx.x >> 5;
    const int warp0   = blockIdx.x * WARPS + wid;
    const int wstride = gridDim.x * WARPS;

    // Issue async loads for tile t into stage.
    auto issueTile = [&](int t, int stage) {
        const long long f4Base = (long long)t * F4_PER_TILE;
        const int rows = n - t * ROWS_PER_TILE;
        const int f4Here = (rows >= ROWS_PER_TILE) ? F4_PER_TILE : ((rows * 7 + 3) >> 2);
        #pragma unroll
        for (int k = 0; k < 4; k++) {
            int idx = k * 32 + lane;
            if (idx < f4Here) cp16(&buf[wid][stage][idx], &x4[f4Base + idx]);
        }
        cp_commit();
    };

    int t = warp0;
    int stage = 0;
    if (t < numTiles) issueTile(t, 0);

    for (; t < numTiles; t += wstride) {
        const int tn = t + wstride;
        if (tn < numTiles) issueTile(tn, stage ^ 1);
        else               cp_commit();          // empty group keeps wait_group 1 correct
        cp_wait1();                              // tile t's data landed (this lane)
        __syncwarp();                            // ... and every lane's

        const float* wb = (const float*)buf[wid][stage];
        const long long outBase = (long long)t * OUT4_PER_TILE;
        const int rowsHere = n - t * ROWS_PER_TILE;

        if (rowsHere >= ROWS_PER_TILE) {
            #pragma unroll
            for (int k = 0; k < 4; k++) {
                int idx = k * 32 + lane;         // 0..127, contiguous output sweep
                int row = idx >> 1;
                float4 v;
                if (idx & 1) {
                    v = make_float4(0.0f, 0.0f, 0.0f, 0.0f);
                } else {
                    float x0 = wb[row * 7 + 0];
                    float x1 = wb[row * 7 + 1];
                    v = make_float4(1.0f + x0, 1.0f - x0, 1.0f + x1, 1.0f - x1);
                }
                __stcs(&out4[outBase + idx], v);
            }
        } else {
            #pragma unroll
            for (int k = 0; k < 4; k++) {
                int idx = k * 32 + lane;
                int row = idx >> 1;
                if (row < rowsHere) {
                    float4 v;
                    if (idx & 1) {
                        v = make_float4(0.0f, 0.0f, 0.0f, 0.0f);
                    } else {
                        float x0 = wb[row * 7 + 0];
                        float x1 = wb[row * 7 + 1];
                        v = make_float4(1.0f + x0, 1.0f - x0, 1.0f + x1, 1.0f - x1);
                    }
                    __stcs(&out4[outBase + idx], v);
                }
            }
        }
        __syncwarp();    // no lane may refill this stage while another still reads it
        stage ^= 1;
    }
}

extern "C" void kernel_launch(void* const* d_in, const int* in_sizes, int n_in,
                              void* d_out, int out_size)
{
    const float4* x4 = (const float4*)d_in[0];   // (B,7) fp32; B*7 divisible by 4
    float4* out4 = (float4*)d_out;               // (B,8) fp32 = 2 float4 per row

    const int n = in_sizes[0] / 7;               // B rows
    const int numTiles = (n + ROWS_PER_TILE - 1) / ROWS_PER_TILE;

    int blocksNeeded = (numTiles + WARPS - 1) / WARPS;
    int blocks = 152 * 8;                        // persistent-ish: 8 blocks/SM on 152 SMs
    if (blocks > blocksNeeded) blocks = blocksNeeded;

    cbf_kernel<<<blocks, THREADS>>>(x4, out4, n, numTiles);
}